// round 1
// baseline (speedup 1.0000x reference)
#include <cuda_runtime.h>
#include <math.h>

#define NQ 10
#define DIM 1024            // 2^NQ amplitudes
#define NP 100              // params per branch
#define FD 256              // feature dim
#define NOUT 30             // 3*NQ expectation values
#define TWO_PI_F 6.2831853071795864769f

// ---------------------------------------------------------------------------
// One CTA per batch sample. Statevector (re/im fp32) lives in shared memory.
// 3 branches computed sequentially in-block, combined at the end.
// ---------------------------------------------------------------------------

// Apply a 1-qubit gate on wire w (PennyLane wire 0 = MSB -> bit position 9-w).
// TYPE: 0 = RX, 1 = RY, 2 = RZ. c = cos(theta/2), s = sin(theta/2).
template <int TYPE>
__device__ __forceinline__ void gate_1q(float* sre, float* sim, int w,
                                        float c, float s) {
    const int p  = 9 - w;
    const int st = 1 << p;
#pragma unroll
    for (int kk = 0; kk < 2; kk++) {
        int k  = threadIdx.x + kk * 256;          // 512 pairs total
        int i0 = ((k >> p) << (p + 1)) | (k & (st - 1));
        int i1 = i0 | st;
        float r0 = sre[i0], m0 = sim[i0];
        float r1 = sre[i1], m1 = sim[i1];
        float nr0, nm0, nr1, nm1;
        if (TYPE == 0) {          // RX: a0' = c a0 - i s a1 ; a1' = -i s a0 + c a1
            nr0 =  c * r0 + s * m1;  nm0 =  c * m0 - s * r1;
            nr1 =  s * m0 + c * r1;  nm1 = -s * r0 + c * m1;
        } else if (TYPE == 1) {   // RY: real rotation
            nr0 = c * r0 - s * r1;   nm0 = c * m0 - s * m1;
            nr1 = s * r0 + c * r1;   nm1 = s * m0 + c * m1;
        } else {                  // RZ: a0' *= e^{-i t/2}, a1' *= e^{+i t/2}
            nr0 = c * r0 + s * m0;   nm0 = c * m0 - s * r0;
            nr1 = c * r1 - s * m1;   nm1 = c * m1 + s * r1;
        }
        sre[i0] = nr0; sim[i0] = nm0;
        sre[i1] = nr1; sim[i1] = nm1;
    }
    __syncthreads();
}

// Controlled-RX: control wire cw, target wire tw. 256 pairs (control bit = 1).
__device__ __forceinline__ void gate_crx(float* sre, float* sim,
                                         int cw, int tw, float c, float s) {
    const int pc = 9 - cw;
    const int pt = 9 - tw;
    const int hi = pc > pt ? pc : pt;
    const int lo = pc > pt ? pt : pc;
    int k = threadIdx.x;                          // 256 pairs, exactly 1/thread
    int i = ((k >> lo) << (lo + 1)) | (k & ((1 << lo) - 1));
    i     = ((i >> hi) << (hi + 1)) | (i & ((1 << hi) - 1));
    int i0 = i | (1 << pc);                       // control=1, target=0
    int i1 = i0 | (1 << pt);
    float r0 = sre[i0], m0 = sim[i0];
    float r1 = sre[i1], m1 = sim[i1];
    sre[i0] =  c * r0 + s * m1;  sim[i0] =  c * m0 - s * r1;
    sre[i1] =  s * m0 + c * r1;  sim[i1] = -s * r0 + c * m1;
    __syncthreads();
}

__global__ __launch_bounds__(256, 4)
void qsb_kernel(const float* __restrict__ x,
                const float* __restrict__ W1, const float* __restrict__ b1,
                const float* __restrict__ W2, const float* __restrict__ b2,
                const float* __restrict__ W3, const float* __restrict__ b3,
                const float* __restrict__ base1, const float* __restrict__ base2,
                const float* __restrict__ base3,
                const float* __restrict__ alpha_r, const float* __restrict__ alpha_i,
                const float* __restrict__ beta_r,  const float* __restrict__ beta_i,
                const float* __restrict__ gamma_r, const float* __restrict__ gamma_i,
                float* __restrict__ out) {
    __shared__ float sx[FD];
    __shared__ float gc[NP], gs[NP];              // cos/sin of theta/2 per gate
    __shared__ float sre[DIM], sim[DIM];
    __shared__ float red[24];                     // 8 warps x 3 partials
    __shared__ float m[3][NOUT];                  // per-branch expectations

    const int tid   = threadIdx.x;
    const int batch = blockIdx.x;
    const int warp  = tid >> 5;
    const int lane  = tid & 31;

    sx[tid] = x[batch * FD + tid];
    __syncthreads();

    const float* Ws[3]    = {W1, W2, W3};
    const float* Bs[3]    = {b1, b2, b3};
    const float* Bases[3] = {base1, base2, base3};

    for (int brn = 0; brn < 3; brn++) {
        // ---- linear layer + sigmoid -> angles -> (cos, sin) of theta/2 ----
        const float* W  = Ws[brn];
        const float* bb = Bs[brn];
        const float* ba = Bases[brn];
        for (int p = warp; p < NP; p += 8) {      // warp-per-param dot product
            float acc = 0.f;
#pragma unroll
            for (int u = 0; u < 8; u++)
                acc += W[p * FD + u * 32 + lane] * sx[u * 32 + lane];
#pragma unroll
            for (int o = 16; o; o >>= 1)
                acc += __shfl_down_sync(0xffffffffu, acc, o);
            if (lane == 0) {
                float t     = acc + bb[p] + ba[p];
                float sig   = 1.f / (1.f + expf(-t));
                float theta = sig * TWO_PI_F;
                float sv, cv;
                sincosf(0.5f * theta, &sv, &cv);
                gc[p] = cv; gs[p] = sv;
            }
        }
        // ---- init |0...0> ----
#pragma unroll
        for (int j = 0; j < 4; j++) {
            int idx = tid + j * 256;
            sre[idx] = (idx == 0) ? 1.f : 0.f;
            sim[idx] = 0.f;
        }
        __syncthreads();                          // params + state visible

        // ---- gate sequence (matches reference order exactly) ----
        int idx = 0;
        for (int layer = 0; layer < 2; layer++) {
            for (int w = 0; w < NQ; w++) {
                gate_1q<0>(sre, sim, w, gc[idx],     gs[idx]);
                gate_1q<1>(sre, sim, w, gc[idx + 1], gs[idx + 1]);
                gate_1q<2>(sre, sim, w, gc[idx + 2], gs[idx + 2]);
                idx += 3;
            }
            for (int i = 0; i < NQ; i++) {
                gate_crx(sre, sim, i, (i + 1) % NQ, gc[idx], gs[idx]);
                idx++;
            }
            for (int i = NQ - 1; i >= 0; i--) {
                gate_crx(sre, sim, i, (i + NQ - 1) % NQ, gc[idx], gs[idx]);
                idx++;
            }
        }

        // ---- expectation values <X_w>, <Y_w>, <Z_w> ----
        for (int w = 0; w < NQ; w++) {
            const int p  = 9 - w;
            const int st = 1 << p;
            float zr = 0.f, zi = 0.f, pz = 0.f;
#pragma unroll
            for (int kk = 0; kk < 2; kk++) {
                int k  = tid + kk * 256;
                int i0 = ((k >> p) << (p + 1)) | (k & (st - 1));
                int i1 = i0 | st;
                float r0 = sre[i0], m0 = sim[i0];
                float r1 = sre[i1], m1 = sim[i1];
                zr += r0 * r1 + m0 * m1;          // Re(conj(a0)*a1)
                zi += r0 * m1 - m0 * r1;          // Im(conj(a0)*a1)
                pz += (r0 * r0 + m0 * m0) - (r1 * r1 + m1 * m1);
            }
#pragma unroll
            for (int o = 16; o; o >>= 1) {
                zr += __shfl_down_sync(0xffffffffu, zr, o);
                zi += __shfl_down_sync(0xffffffffu, zi, o);
                pz += __shfl_down_sync(0xffffffffu, pz, o);
            }
            if (lane == 0) {
                red[warp] = zr; red[8 + warp] = zi; red[16 + warp] = pz;
            }
            __syncthreads();
            if (tid == 0) {
                float a = 0.f, b = 0.f, c = 0.f;
#pragma unroll
                for (int q = 0; q < 8; q++) {
                    a += red[q]; b += red[8 + q]; c += red[16 + q];
                }
                m[brn][w]          = 2.f * a;
                m[brn][NQ + w]     = 2.f * b;
                m[brn][2 * NQ + w] = c;
            }
            __syncthreads();
        }
    }

    // ---- superposition combine ----
    if (tid < NOUT) {
        float arv = alpha_r[0], aiv = alpha_i[0];
        float brv = beta_r[0],  biv = beta_i[0];
        float grv = gamma_r[0], giv = gamma_i[0];
        float nrm = sqrtf(arv * arv + aiv * aiv + brv * brv + biv * biv +
                          grv * grv + giv * giv + 1e-9f);
        float inv = 1.f / nrm;
        float re = (arv * m[0][tid] + brv * m[1][tid] + grv * m[2][tid]) * inv;
        float im = (aiv * m[0][tid] + biv * m[1][tid] + giv * m[2][tid]) * inv;
        out[batch * NOUT + tid] = sqrtf(re * re + im * im);
    }
}

extern "C" void kernel_launch(void* const* d_in, const int* in_sizes, int n_in,
                              void* d_out, int out_size) {
    const float* x      = (const float*)d_in[0];
    const float* W1     = (const float*)d_in[1];
    const float* b1     = (const float*)d_in[2];
    const float* W2     = (const float*)d_in[3];
    const float* b2     = (const float*)d_in[4];
    const float* W3     = (const float*)d_in[5];
    const float* b3     = (const float*)d_in[6];
    const float* base1  = (const float*)d_in[7];
    const float* base2  = (const float*)d_in[8];
    const float* base3  = (const float*)d_in[9];
    const float* ar     = (const float*)d_in[10];
    const float* ai     = (const float*)d_in[11];
    const float* br     = (const float*)d_in[12];
    const float* bi     = (const float*)d_in[13];
    const float* gr     = (const float*)d_in[14];
    const float* gi     = (const float*)d_in[15];
    float* out = (float*)d_out;

    qsb_kernel<<<256, 256>>>(x, W1, b1, W2, b2, W3, b3, base1, base2, base3,
                             ar, ai, br, bi, gr, gi, out);
}

// round 2
// speedup vs baseline: 2.0323x; 2.0323x over previous
#include <cuda_runtime.h>
#include <math.h>

#define NQ 10
#define NP 100
#define FD 256
#define NOUT 30
#define TWO_PI_F 6.2831853071795864769f

// Named barrier per branch-group (ids 1..3), 256 threads each.
__device__ __forceinline__ void gbar(int g) {
    asm volatile("bar.sync %0, 256;" :: "r"(g + 1) : "memory");
}

// Fused SU(2) 1q gate on amplitude-bit b.
// U = [[u00, u01], [-conj(u01), conj(u00)]]
__device__ __forceinline__ void apply_u(int b, float u00r, float u00i,
                                        float u01r, float u01i,
                                        float ar[4], float ai[4],
                                        int gtid, float* B, int g) {
    if (b < 2) {                                  // local register pairs
#pragma unroll
        for (int t = 0; t < 2; t++) {
            int j0 = (b == 0) ? t * 2 : t;
            int j1 = j0 | (1 << b);
            float a0r = ar[j0], a0i = ai[j0], a1r = ar[j1], a1i = ai[j1];
            ar[j0] =  u00r * a0r - u00i * a0i + u01r * a1r - u01i * a1i;
            ai[j0] =  u00r * a0i + u00i * a0r + u01r * a1i + u01i * a1r;
            ar[j1] = -u01r * a0r - u01i * a0i + u00r * a1r + u00i * a1i;
            ai[j1] = -u01r * a0i + u01i * a0r + u00r * a1i - u00i * a1r;
        }
    } else if (b < 7) {                           // lane bits: warp shuffle
        int m = 1 << (b - 2);
        int s = (gtid >> (b - 2)) & 1;
        float cwr = u00r, cwi = s ? -u00i : u00i;
        float cpr = s ? -u01r : u01r, cpi = u01i;
#pragma unroll
        for (int j = 0; j < 4; j++) {
            float pr = __shfl_xor_sync(0xffffffffu, ar[j], m);
            float pi = __shfl_xor_sync(0xffffffffu, ai[j], m);
            float orr = ar[j], oii = ai[j];
            ar[j] = cwr * orr - cwi * oii + cpr * pr - cpi * pi;
            ai[j] = cwr * oii + cwi * orr + cpr * pi + cpi * pr;
        }
    } else {                                      // warp bits: smem exchange
        int m = 1 << (b - 2);
        int s = (gtid >> (b - 2)) & 1;
        float4* A4 = (float4*)B;
        float4* I4 = (float4*)(B + 1024);
        A4[gtid] = make_float4(ar[0], ar[1], ar[2], ar[3]);
        I4[gtid] = make_float4(ai[0], ai[1], ai[2], ai[3]);
        gbar(g);
        float4 pa = A4[gtid ^ m];
        float4 pb = I4[gtid ^ m];
        float prr[4] = {pa.x, pa.y, pa.z, pa.w};
        float pii[4] = {pb.x, pb.y, pb.z, pb.w};
        float cwr = u00r, cwi = s ? -u00i : u00i;
        float cpr = s ? -u01r : u01r, cpi = u01i;
#pragma unroll
        for (int j = 0; j < 4; j++) {
            float orr = ar[j], oii = ai[j];
            ar[j] = cwr * orr - cwi * oii + cpr * prr[j] - cpi * pii[j];
            ai[j] = cwr * oii + cwi * orr + cpr * pii[j] + cpi * prr[j];
        }
        gbar(g);
    }
}

// Controlled-RX: control bit pc, target bit pt.
// Update (where control==1): a' = c*a_own + s*i_terms of partner (RX symmetric).
__device__ __forceinline__ void apply_crx(int pc, int pt, float c, float s,
                                          float ar[4], float ai[4],
                                          int gtid, float* B, int g) {
    bool tc = (pc >= 2) ? (((gtid >> (pc - 2)) & 1) != 0) : true;
    if (pt < 2) {                                 // local target
#pragma unroll
        for (int t = 0; t < 2; t++) {
            int j0 = (pt == 0) ? t * 2 : t;
            int j1 = j0 | (1 << pt);
            bool upd = tc && (pc < 2 ? (((j0 >> pc) & 1) != 0) : true);
            if (upd) {
                float a0r = ar[j0], a0i = ai[j0], a1r = ar[j1], a1i = ai[j1];
                ar[j0] = c * a0r + s * a1i;  ai[j0] = c * a0i - s * a1r;
                ar[j1] = c * a1r + s * a0i;  ai[j1] = c * a1i - s * a0r;
            }
        }
    } else if (pt < 7) {                          // lane target: shuffle
        int m = 1 << (pt - 2);
#pragma unroll
        for (int j = 0; j < 4; j++) {
            float pr = __shfl_xor_sync(0xffffffffu, ar[j], m);
            float pi = __shfl_xor_sync(0xffffffffu, ai[j], m);
            bool upd = tc && (pc < 2 ? (((j >> pc) & 1) != 0) : true);
            if (upd) {
                float orr = ar[j], oii = ai[j];
                ar[j] = c * orr + s * pi;
                ai[j] = c * oii - s * pr;
            }
        }
    } else {                                      // warp target: smem exchange
        int m = 1 << (pt - 2);
        float4* A4 = (float4*)B;
        float4* I4 = (float4*)(B + 1024);
        A4[gtid] = make_float4(ar[0], ar[1], ar[2], ar[3]);
        I4[gtid] = make_float4(ai[0], ai[1], ai[2], ai[3]);
        gbar(g);
        float4 pa = A4[gtid ^ m];
        float4 pb = I4[gtid ^ m];
        float prr[4] = {pa.x, pa.y, pa.z, pa.w};
        float pii[4] = {pb.x, pb.y, pb.z, pb.w};
#pragma unroll
        for (int j = 0; j < 4; j++) {
            bool upd = tc && (pc < 2 ? (((j >> pc) & 1) != 0) : true);
            if (upd) {
                float orr = ar[j], oii = ai[j];
                ar[j] = c * orr + s * prr[j] * 0.0f + s * pii[j]; // keep form
                ar[j] = c * orr + s * pii[j];
                ai[j] = c * oii - s * prr[j];
            }
        }
        gbar(g);
    }
}

__global__ __launch_bounds__(768, 1)
void qsb_kernel(const float* __restrict__ x,
                const float* __restrict__ W1, const float* __restrict__ b1,
                const float* __restrict__ W2, const float* __restrict__ b2,
                const float* __restrict__ W3, const float* __restrict__ b3,
                const float* __restrict__ base1, const float* __restrict__ base2,
                const float* __restrict__ base3,
                const float* __restrict__ alpha_r, const float* __restrict__ alpha_i,
                const float* __restrict__ beta_r,  const float* __restrict__ beta_i,
                const float* __restrict__ gamma_r, const float* __restrict__ gamma_i,
                float* __restrict__ out) {
    __shared__ float sx[FD];
    __shared__ float gc[3][NP], gs[3][NP];
    __shared__ float buf[3][2048];                // per-group exchange / dump
    __shared__ float wred[3][8][NOUT];
    __shared__ float mres[3][NOUT];

    const int tid   = threadIdx.x;
    const int g     = tid >> 8;                   // branch group 0..2
    const int gtid  = tid & 255;
    const int lane  = tid & 31;
    const int gwarp = gtid >> 5;
    const int batch = blockIdx.x;

    if (tid < FD) sx[tid] = x[batch * FD + tid];
    __syncthreads();

    const float* W  = (g == 0) ? W1 : ((g == 1) ? W2 : W3);
    const float* bb = (g == 0) ? b1 : ((g == 1) ? b2 : b3);
    const float* ba = (g == 0) ? base1 : ((g == 1) ? base2 : base3);

    // ---- params: linear + sigmoid -> (cos, sin)(theta/2) ----
    for (int p = gwarp; p < NP; p += 8) {
        float acc = 0.f;
#pragma unroll
        for (int u = 0; u < 8; u++)
            acc += W[p * FD + u * 32 + lane] * sx[u * 32 + lane];
#pragma unroll
        for (int o = 16; o; o >>= 1)
            acc += __shfl_down_sync(0xffffffffu, acc, o);
        if (lane == 0) {
            float t     = acc + bb[p] + ba[p];
            float sig   = 1.f / (1.f + expf(-t));
            float theta = sig * TWO_PI_F;
            float sv, cv;
            sincosf(0.5f * theta, &sv, &cv);
            gc[g][p] = cv; gs[g][p] = sv;
        }
    }
    gbar(g);

    // ---- state in registers: amp index = (gtid << 2) | j ----
    float ar[4], ai[4];
#pragma unroll
    for (int j = 0; j < 4; j++) { ar[j] = 0.f; ai[j] = 0.f; }
    if (gtid == 0) ar[0] = 1.f;

    float* B = buf[g];

    int idx = 0;
#pragma unroll
    for (int layer = 0; layer < 2; layer++) {
#pragma unroll
        for (int w = 0; w < NQ; w++) {
            int b = 9 - w;
            float c0 = gc[g][idx],     s0 = gs[g][idx];
            float c1 = gc[g][idx + 1], s1 = gs[g][idx + 1];
            float cz = gc[g][idx + 2], sz = gs[g][idx + 2];
            idx += 3;
            // U = Rz * Ry * Rx (SU(2): store u00, u01)
            float u00r =  cz * c1 * c0 + sz * s1 * s0;
            float u00i =  cz * s1 * s0 - sz * c1 * c0;
            float u01r = -(cz * s1 * c0 + sz * c1 * s0);
            float u01i =  sz * s1 * c0 - cz * c1 * s0;
            apply_u(b, u00r, u00i, u01r, u01i, ar, ai, gtid, B, g);
        }
#pragma unroll
        for (int i = 0; i < NQ; i++) {
            apply_crx(9 - i, 9 - ((i + 1) % NQ), gc[g][idx], gs[g][idx],
                      ar, ai, gtid, B, g);
            idx++;
        }
#pragma unroll
        for (int i = NQ - 1; i >= 0; i--) {
            apply_crx(9 - i, 9 - ((i + 9) % NQ), gc[g][idx], gs[g][idx],
                      ar, ai, gtid, B, g);
            idx++;
        }
    }

    // ---- dump state, compute expectations ----
    {
        float4* A4 = (float4*)B;
        float4* I4 = (float4*)(B + 1024);
        A4[gtid] = make_float4(ar[0], ar[1], ar[2], ar[3]);
        I4[gtid] = make_float4(ai[0], ai[1], ai[2], ai[3]);
        gbar(g);
    }
#pragma unroll
    for (int w = 0; w < NQ; w++) {
        int p = 9 - w;
        float zr = 0.f, zi = 0.f, pz = 0.f;
#pragma unroll
        for (int kk = 0; kk < 2; kk++) {
            int k  = gtid + kk * 256;
            int i0 = ((k >> p) << (p + 1)) | (k & ((1 << p) - 1));
            int i1 = i0 | (1 << p);
            float r0 = B[i0], m0 = B[1024 + i0];
            float r1 = B[i1], m1 = B[1024 + i1];
            zr += r0 * r1 + m0 * m1;
            zi += r0 * m1 - m0 * r1;
            pz += (r0 * r0 + m0 * m0) - (r1 * r1 + m1 * m1);
        }
#pragma unroll
        for (int o = 16; o; o >>= 1) {
            zr += __shfl_down_sync(0xffffffffu, zr, o);
            zi += __shfl_down_sync(0xffffffffu, zi, o);
            pz += __shfl_down_sync(0xffffffffu, pz, o);
        }
        if (lane == 0) {
            wred[g][gwarp][w]          = zr;
            wred[g][gwarp][NQ + w]     = zi;
            wred[g][gwarp][2 * NQ + w] = pz;
        }
    }
    gbar(g);
    if (gtid < NOUT) {
        float a = 0.f;
#pragma unroll
        for (int q = 0; q < 8; q++) a += wred[g][q][gtid];
        mres[g][gtid] = (gtid < 2 * NQ) ? 2.f * a : a;
    }
    __syncthreads();

    // ---- superposition combine ----
    if (tid < NOUT) {
        float arv = alpha_r[0], aiv = alpha_i[0];
        float brv = beta_r[0],  biv = beta_i[0];
        float grv = gamma_r[0], giv = gamma_i[0];
        float nrm = sqrtf(arv * arv + aiv * aiv + brv * brv + biv * biv +
                          grv * grv + giv * giv + 1e-9f);
        float inv = 1.f / nrm;
        float re = (arv * mres[0][tid] + brv * mres[1][tid] + grv * mres[2][tid]) * inv;
        float im = (aiv * mres[0][tid] + biv * mres[1][tid] + giv * mres[2][tid]) * inv;
        out[batch * NOUT + tid] = sqrtf(re * re + im * im);
    }
}

extern "C" void kernel_launch(void* const* d_in, const int* in_sizes, int n_in,
                              void* d_out, int out_size) {
    const float* x      = (const float*)d_in[0];
    const float* W1     = (const float*)d_in[1];
    const float* b1     = (const float*)d_in[2];
    const float* W2     = (const float*)d_in[3];
    const float* b2     = (const float*)d_in[4];
    const float* W3     = (const float*)d_in[5];
    const float* b3     = (const float*)d_in[6];
    const float* base1  = (const float*)d_in[7];
    const float* base2  = (const float*)d_in[8];
    const float* base3  = (const float*)d_in[9];
    const float* ar     = (const float*)d_in[10];
    const float* ai     = (const float*)d_in[11];
    const float* br     = (const float*)d_in[12];
    const float* bi     = (const float*)d_in[13];
    const float* gr     = (const float*)d_in[14];
    const float* gi     = (const float*)d_in[15];
    float* out = (float*)d_out;

    qsb_kernel<<<256, 768>>>(x, W1, b1, W2, b2, W3, b3, base1, base2, base3,
                             ar, ai, br, bi, gr, gi, out);
}